// round 1
// baseline (speedup 1.0000x reference)
#include <cuda_runtime.h>
#include <math_constants.h>
#include <math.h>

#define TOKENS 16384
#define HIDDEN 7168
#define NEXP   256
#define TOPK   8

#define BM 128
#define BN 128
#define BK 8

// Scratch for router logits (16384 x 256 fp32 = 16.8 MB)
__device__ float g_logits[(size_t)TOKENS * NEXP];

// ---------------------------------------------------------------------------
// Kernel 1: fp32 SGEMM  C[m][n] = sum_k A[m][k] * B[n][k]
// A = hidden [TOKENS, HIDDEN] row-major, B = weight [NEXP, HIDDEN] row-major.
// 128x128 block tile, BK=8, 256 threads, 8x8 per-thread tile (4+4 split to
// reduce shared-memory bank conflicts), single-sync double buffering.
// ---------------------------------------------------------------------------
__global__ __launch_bounds__(256)
void gemm_kernel(const float* __restrict__ A, const float* __restrict__ B)
{
    __shared__ float As[2][BK][BM];
    __shared__ float Bs[2][BK][BN];

    const int bm  = blockIdx.x * BM;
    const int bn  = blockIdx.y * BN;
    const int tid = threadIdx.x;
    const int tx  = tid & 15;   // 0..15 -> expert cols
    const int ty  = tid >> 4;   // 0..15 -> token rows

    // Global-load mapping: each thread loads one float4 of A and one of B
    const int ldrow = tid >> 1;        // 0..127
    const int ldcol = (tid & 1) * 4;   // 0 or 4

    const float* Aptr = A + (size_t)(bm + ldrow) * HIDDEN + ldcol;
    const float* Bptr = B + (size_t)(bn + ldrow) * HIDDEN + ldcol;

    float acc[8][8];
    #pragma unroll
    for (int i = 0; i < 8; i++)
        #pragma unroll
        for (int j = 0; j < 8; j++) acc[i][j] = 0.0f;

    // Preload tile 0
    {
        float4 a4 = *(const float4*)Aptr;
        float4 b4 = *(const float4*)Bptr;
        As[0][ldcol + 0][ldrow] = a4.x; As[0][ldcol + 1][ldrow] = a4.y;
        As[0][ldcol + 2][ldrow] = a4.z; As[0][ldcol + 3][ldrow] = a4.w;
        Bs[0][ldcol + 0][ldrow] = b4.x; Bs[0][ldcol + 1][ldrow] = b4.y;
        Bs[0][ldcol + 2][ldrow] = b4.z; Bs[0][ldcol + 3][ldrow] = b4.w;
    }
    __syncthreads();

    const int NK = HIDDEN / BK;  // 896
    int buf = 0;
    for (int kt = 0; kt < NK; kt++) {
        float4 na, nb;
        const bool has_next = (kt + 1 < NK);
        if (has_next) {
            na = *(const float4*)(Aptr + (size_t)(kt + 1) * BK);
            nb = *(const float4*)(Bptr + (size_t)(kt + 1) * BK);
        }
        #pragma unroll
        for (int k = 0; k < BK; k++) {
            float ar[8], br[8];
            *(float4*)&ar[0] = *(const float4*)&As[buf][k][ty * 4];
            *(float4*)&ar[4] = *(const float4*)&As[buf][k][ty * 4 + 64];
            *(float4*)&br[0] = *(const float4*)&Bs[buf][k][tx * 4];
            *(float4*)&br[4] = *(const float4*)&Bs[buf][k][tx * 4 + 64];
            #pragma unroll
            for (int i = 0; i < 8; i++)
                #pragma unroll
                for (int j = 0; j < 8; j++)
                    acc[i][j] += ar[i] * br[j];
        }
        if (has_next) {
            const int nbuf = buf ^ 1;
            As[nbuf][ldcol + 0][ldrow] = na.x; As[nbuf][ldcol + 1][ldrow] = na.y;
            As[nbuf][ldcol + 2][ldrow] = na.z; As[nbuf][ldcol + 3][ldrow] = na.w;
            Bs[nbuf][ldcol + 0][ldrow] = nb.x; Bs[nbuf][ldcol + 1][ldrow] = nb.y;
            Bs[nbuf][ldcol + 2][ldrow] = nb.z; Bs[nbuf][ldcol + 3][ldrow] = nb.w;
            __syncthreads();
            buf = nbuf;
        }
    }

    // Epilogue: rows ty*4+{0..3}, ty*4+64+{0..3}; cols tx*4+{0..3}, tx*4+64+{0..3}
    #pragma unroll
    for (int i = 0; i < 8; i++) {
        const int r = bm + ty * 4 + ((i < 4) ? i : (60 + i));  // i>=4 -> 64+(i-4)
        float* C = g_logits + (size_t)r * NEXP + bn;
        *(float4*)(C + tx * 4)      = make_float4(acc[i][0], acc[i][1], acc[i][2], acc[i][3]);
        *(float4*)(C + tx * 4 + 64) = make_float4(acc[i][4], acc[i][5], acc[i][6], acc[i][7]);
    }
}

// ---------------------------------------------------------------------------
// Kernel 2: routing. One warp per token. Lane l owns experts [8l, 8l+8)
// (all inside group l>>2; 4 lanes per group of 32 experts).
// Matches jax.lax.top_k semantics: stable descending, ties -> lowest index.
// ---------------------------------------------------------------------------
__global__ __launch_bounds__(256)
void routing_kernel(const float* __restrict__ bias, float* __restrict__ out,
                    int write_idx)
{
    const unsigned FULL = 0xffffffffu;
    const int lane  = threadIdx.x & 31;
    const int warp  = threadIdx.x >> 5;
    const int token = blockIdx.x * 8 + warp;

    const float* row = g_logits + (size_t)token * NEXP + lane * 8;
    float4 l0 = *(const float4*)row;
    float4 l1 = *(const float4*)(row + 4);
    float4 b0 = *(const float4*)(bias + lane * 8);
    float4 b1 = *(const float4*)(bias + lane * 8 + 4);

    float lv[8] = {l0.x, l0.y, l0.z, l0.w, l1.x, l1.y, l1.z, l1.w};
    float bb[8] = {b0.x, b0.y, b0.z, b0.w, b1.x, b1.y, b1.z, b1.w};
    float sc[8], s4[8];
    #pragma unroll
    for (int i = 0; i < 8; i++) {
        float s = 1.0f / (1.0f + expf(-lv[i]));
        sc[i] = s;             // sigmoid score (routing weight source)
        s4[i] = s + bb[i];     // score_for_choice
    }

    // ---- per-lane top-2 of s4 ----
    float m1 = -CUDART_INF_F, m2 = -CUDART_INF_F;
    #pragma unroll
    for (int i = 0; i < 8; i++) {
        float v  = s4[i];
        float lo = fminf(v, m1);
        m1 = fmaxf(v, m1);
        m2 = fmaxf(m2, lo);
    }
    // merge top-2 across the 4 lanes of the group (xor 1, xor 2 stay in group)
    #pragma unroll
    for (int d = 1; d <= 2; d <<= 1) {
        float o1 = __shfl_xor_sync(FULL, m1, d);
        float o2 = __shfl_xor_sync(FULL, m2, d);
        float n1 = fmaxf(m1, o1);
        float n2 = fmaxf(fminf(m1, o1), fmaxf(m2, o2));
        m1 = n1; m2 = n2;
    }
    const float gs = m1 + m2;   // identical on all 4 lanes of the group
    const int   g  = lane >> 2;

    // ---- rank groups, keep top-4 (ties -> lower group index wins) ----
    int rank = 0;
    #pragma unroll
    for (int j = 0; j < 8; j++) {
        float gj = __shfl_sync(FULL, gs, j * 4);
        rank += (gj > gs) || (gj == gs && j < g);
    }
    if (rank >= 4) {
        #pragma unroll
        for (int i = 0; i < 8; i++) s4[i] = -CUDART_INF_F;
    }

    // ---- global top-8 over s4 (ties -> lower expert index) ----
    float wsum = 0.0f, my_w = 0.0f;
    int   my_ix = 0;
    #pragma unroll
    for (int t = 0; t < 8; t++) {
        // per-lane argmax (ascending scan + strict > keeps lowest index on tie)
        float bv = s4[0]; int bp = 0;
        #pragma unroll
        for (int i = 1; i < 8; i++) {
            if (s4[i] > bv) { bv = s4[i]; bp = i; }
        }
        float v  = bv;
        int   ix = lane * 8 + bp;
        #pragma unroll
        for (int d = 16; d; d >>= 1) {
            float ov = __shfl_xor_sync(FULL, v, d);
            int   oi = __shfl_xor_sync(FULL, ix, d);
            if (ov > v || (ov == v && oi < ix)) { v = ov; ix = oi; }
        }
        const int opos  = ix & 7;
        const int olane = ix >> 3;
        // remove winner (static-indexed predicated writes, no local spill)
        #pragma unroll
        for (int i = 0; i < 8; i++)
            if (lane == olane && i == opos) s4[i] = -CUDART_INF_F;
        // routing weight = raw sigmoid score of winner
        float cand = sc[0];
        #pragma unroll
        for (int i = 1; i < 8; i++)
            if (i == opos) cand = sc[i];
        float w = __shfl_sync(FULL, cand, olane);
        wsum += w;
        if (lane == t) { my_w = w; my_ix = ix; }
    }

    const float scale = 2.5f / (wsum + 1e-20f);
    if (lane < TOPK) {
        out[(size_t)token * TOPK + lane] = my_w * scale;
        if (write_idx)
            out[(size_t)TOKENS * TOPK + (size_t)token * TOPK + lane] = (float)my_ix;
    }
}

// ---------------------------------------------------------------------------
extern "C" void kernel_launch(void* const* d_in, const int* in_sizes, int n_in,
                              void* d_out, int out_size)
{
    const float* hs   = (const float*)d_in[0];  // [16384, 7168]
    const float* w    = (const float*)d_in[1];  // [256, 7168]
    const float* bias = (const float*)d_in[2];  // [256]
    float* out = (float*)d_out;

    dim3 grid(TOKENS / BM, NEXP / BN);  // (128, 2)
    gemm_kernel<<<grid, 256>>>(hs, w);

    // Output contract: tuple (routing_weights [T,8] f32, selected_experts [T,8]).
    // Assume concatenated flat as the output dtype; write indices only if the
    // buffer has room for both halves.
    const int write_idx = (out_size >= TOKENS * TOPK * 2) ? 1 : 0;
    routing_kernel<<<TOKENS / 8, 256>>>(bias, out, write_idx);
}